// round 1
// baseline (speedup 1.0000x reference)
#include <cuda_runtime.h>

// ---------------------------------------------------------------------------
// MultiHeadAttention: b=2, t=2048, e=512, h=8 (per-head dim = 512!)
//   q,k,v = (x @ W^T) reshaped (b,h,t,e)
//   scores = q k^T / sqrt(512), causal mask, softmax
//   out = (softmax @ v) concat -> @ Wc^T + bc
// Baseline fp32 SIMT tiled GEMMs (128x128x8, 8x8/thread).
// ---------------------------------------------------------------------------

#define NEG_INF (-1e30f)
#define SCALE 0.044194173824159216f   // 1/sqrt(512)

// Scratch (device globals; allocation-free at runtime)
static __device__ float g_q[16 * 2048 * 512];      // 64 MB  (b*h, t, e)
static __device__ float g_k[16 * 2048 * 512];      // 64 MB
static __device__ float g_v[16 * 2048 * 512];      // 64 MB
static __device__ float g_p[16u * 2048 * 2048];    // 256 MB scores/probs
static __device__ float g_att[16 * 2048 * 512];    // 64 MB  attention out

// ---------------------------------------------------------------------------
// QKV projection: C[i,j] = sum_k X[i,k] * W[j,k], M=N=4096, K=512
// Output remapped to (b,h,t,e) layout. mode: 0->g_q, 1->g_k, 2->g_v
// ---------------------------------------------------------------------------
__global__ __launch_bounds__(256) void proj_kernel(const float* __restrict__ X,
                                                   const float* __restrict__ W,
                                                   int mode)
{
    __shared__ float As[8][128];
    __shared__ float Bs[8][128];

    float* out = (mode == 0) ? g_q : (mode == 1) ? g_k : g_v;

    const int m0 = blockIdx.y * 128;
    const int n0 = blockIdx.x * 128;
    const int tid = threadIdx.x;
    const int tx = tid & 15, ty = tid >> 4;
    const int lrow = tid >> 1;
    const int lk4  = (tid & 1) * 4;

    float acc[8][8];
#pragma unroll
    for (int i = 0; i < 8; i++)
#pragma unroll
        for (int j = 0; j < 8; j++) acc[i][j] = 0.f;

    for (int k0 = 0; k0 < 512; k0 += 8) {
        float4 a = *(const float4*)(X + (m0 + lrow) * 512 + k0 + lk4);
        float4 b = *(const float4*)(W + (n0 + lrow) * 512 + k0 + lk4);
        As[lk4 + 0][lrow] = a.x; As[lk4 + 1][lrow] = a.y;
        As[lk4 + 2][lrow] = a.z; As[lk4 + 3][lrow] = a.w;
        Bs[lk4 + 0][lrow] = b.x; Bs[lk4 + 1][lrow] = b.y;
        Bs[lk4 + 2][lrow] = b.z; Bs[lk4 + 3][lrow] = b.w;
        __syncthreads();
#pragma unroll
        for (int kk = 0; kk < 8; kk++) {
            float a0[8], b0[8];
            *(float4*)&a0[0] = *(const float4*)&As[kk][ty * 8];
            *(float4*)&a0[4] = *(const float4*)&As[kk][ty * 8 + 4];
            *(float4*)&b0[0] = *(const float4*)&Bs[kk][tx * 8];
            *(float4*)&b0[4] = *(const float4*)&Bs[kk][tx * 8 + 4];
#pragma unroll
            for (int i = 0; i < 8; i++)
#pragma unroll
                for (int j = 0; j < 8; j++) acc[i][j] += a0[i] * b0[j];
        }
        __syncthreads();
    }

#pragma unroll
    for (int i = 0; i < 8; i++) {
        int gi = m0 + ty * 8 + i;          // token index
        int bb = gi >> 11, t = gi & 2047;
#pragma unroll
        for (int j4 = 0; j4 < 2; j4++) {
            int gj = n0 + tx * 8 + j4 * 4; // h*512 + e
            int h = gj >> 9, e = gj & 511;
            float4 v4 = make_float4(acc[i][j4 * 4 + 0], acc[i][j4 * 4 + 1],
                                    acc[i][j4 * 4 + 2], acc[i][j4 * 4 + 3]);
            *(float4*)(out + (((bb * 8 + h) * 2048 + t) << 9) + e) = v4;
        }
    }
}

// ---------------------------------------------------------------------------
// Scores: per head z, S = Q K^T * scale with causal mask. M=N=2048, K=512.
// Blocks fully above diagonal skipped.
// ---------------------------------------------------------------------------
__global__ __launch_bounds__(256) void scores_kernel()
{
    const int z  = blockIdx.z;
    const int m0 = blockIdx.y * 128;
    const int n0 = blockIdx.x * 128;
    if (n0 > m0 + 127) return;   // fully masked tile

    const float* Q = g_q + z * 1048576;
    const float* K = g_k + z * 1048576;
    float* P = g_p + (size_t)z * 4194304;

    __shared__ float As[8][128];
    __shared__ float Bs[8][128];

    const int tid = threadIdx.x;
    const int tx = tid & 15, ty = tid >> 4;
    const int lrow = tid >> 1;
    const int lk4  = (tid & 1) * 4;

    float acc[8][8];
#pragma unroll
    for (int i = 0; i < 8; i++)
#pragma unroll
        for (int j = 0; j < 8; j++) acc[i][j] = 0.f;

    for (int k0 = 0; k0 < 512; k0 += 8) {
        float4 a = *(const float4*)(Q + (m0 + lrow) * 512 + k0 + lk4);
        float4 b = *(const float4*)(K + (n0 + lrow) * 512 + k0 + lk4);
        As[lk4 + 0][lrow] = a.x; As[lk4 + 1][lrow] = a.y;
        As[lk4 + 2][lrow] = a.z; As[lk4 + 3][lrow] = a.w;
        Bs[lk4 + 0][lrow] = b.x; Bs[lk4 + 1][lrow] = b.y;
        Bs[lk4 + 2][lrow] = b.z; Bs[lk4 + 3][lrow] = b.w;
        __syncthreads();
#pragma unroll
        for (int kk = 0; kk < 8; kk++) {
            float a0[8], b0[8];
            *(float4*)&a0[0] = *(const float4*)&As[kk][ty * 8];
            *(float4*)&a0[4] = *(const float4*)&As[kk][ty * 8 + 4];
            *(float4*)&b0[0] = *(const float4*)&Bs[kk][tx * 8];
            *(float4*)&b0[4] = *(const float4*)&Bs[kk][tx * 8 + 4];
#pragma unroll
            for (int i = 0; i < 8; i++)
#pragma unroll
                for (int j = 0; j < 8; j++) acc[i][j] += a0[i] * b0[j];
        }
        __syncthreads();
    }

#pragma unroll
    for (int i = 0; i < 8; i++) {
        int r = m0 + ty * 8 + i;
#pragma unroll
        for (int j = 0; j < 8; j++) {
            int c = n0 + tx * 8 + j;
            P[r * 2048 + c] = (c <= r) ? acc[i][j] * SCALE : NEG_INF;
        }
    }
}

// ---------------------------------------------------------------------------
// Softmax: one block per row; processes cols [0, diag-tile end).
// Masked entries (NEG_INF) become 0 naturally.
// ---------------------------------------------------------------------------
__global__ __launch_bounds__(256) void softmax_kernel()
{
    const int row = blockIdx.x;              // 0..32767
    const int z = row >> 11;
    const int q = row & 2047;
    float* P = g_p + (size_t)z * 4194304 + q * 2048;
    const int end = ((q >> 7) + 1) << 7;     // up to and including diagonal tile

    const int tid = threadIdx.x;
    __shared__ float red[256];

    float m = -3.4e38f;
    for (int c = tid; c < end; c += 256) m = fmaxf(m, P[c]);
    red[tid] = m; __syncthreads();
    for (int s = 128; s > 0; s >>= 1) {
        if (tid < s) red[tid] = fmaxf(red[tid], red[tid + s]);
        __syncthreads();
    }
    m = red[0]; __syncthreads();

    float vals[8];
    int cnt = 0;
    float sum = 0.f;
    for (int c = tid; c < end; c += 256) {
        float e = expf(P[c] - m);
        vals[cnt++] = e;
        sum += e;
    }
    red[tid] = sum; __syncthreads();
    for (int s = 128; s > 0; s >>= 1) {
        if (tid < s) red[tid] += red[tid + s];
        __syncthreads();
    }
    const float inv = 1.f / red[0];
    cnt = 0;
    for (int c = tid; c < end; c += 256) P[c] = vals[cnt++] * inv;
}

// ---------------------------------------------------------------------------
// PV: per head, O = P @ V. M=2048, N=512, K truncated at (by+1)*128 (causal).
// ---------------------------------------------------------------------------
__global__ __launch_bounds__(256) void pv_kernel()
{
    const int z  = blockIdx.z;
    const int m0 = blockIdx.y * 128;
    const int n0 = blockIdx.x * 128;
    const int kend = (blockIdx.y + 1) * 128;

    const float* P = g_p + (size_t)z * 4194304;
    const float* V = g_v + z * 1048576;
    float* O = g_att + z * 1048576;

    __shared__ float As[8][128];
    __shared__ float Bs[8][128];

    const int tid = threadIdx.x;
    const int tx = tid & 15, ty = tid >> 4;
    const int lrow = tid >> 1;
    const int lk4  = (tid & 1) * 4;
    const int kb = tid >> 5;          // 0..7
    const int nb = (tid & 31) * 4;    // 0..124

    float acc[8][8];
#pragma unroll
    for (int i = 0; i < 8; i++)
#pragma unroll
        for (int j = 0; j < 8; j++) acc[i][j] = 0.f;

    for (int k0 = 0; k0 < kend; k0 += 8) {
        float4 a = *(const float4*)(P + (m0 + lrow) * 2048 + k0 + lk4);
        As[lk4 + 0][lrow] = a.x; As[lk4 + 1][lrow] = a.y;
        As[lk4 + 2][lrow] = a.z; As[lk4 + 3][lrow] = a.w;
        float4 b = *(const float4*)(V + (k0 + kb) * 512 + n0 + nb);
        *(float4*)&Bs[kb][nb] = b;
        __syncthreads();
#pragma unroll
        for (int kk = 0; kk < 8; kk++) {
            float a0[8], b0[8];
            *(float4*)&a0[0] = *(const float4*)&As[kk][ty * 8];
            *(float4*)&a0[4] = *(const float4*)&As[kk][ty * 8 + 4];
            *(float4*)&b0[0] = *(const float4*)&Bs[kk][tx * 8];
            *(float4*)&b0[4] = *(const float4*)&Bs[kk][tx * 8 + 4];
#pragma unroll
            for (int i = 0; i < 8; i++)
#pragma unroll
                for (int j = 0; j < 8; j++) acc[i][j] += a0[i] * b0[j];
        }
        __syncthreads();
    }

#pragma unroll
    for (int i = 0; i < 8; i++) {
        int r = m0 + ty * 8 + i;
#pragma unroll
        for (int j4 = 0; j4 < 2; j4++) {
            int c = n0 + tx * 8 + j4 * 4;
            float4 v4 = make_float4(acc[i][j4 * 4 + 0], acc[i][j4 * 4 + 1],
                                    acc[i][j4 * 4 + 2], acc[i][j4 * 4 + 3]);
            *(float4*)(O + r * 512 + c) = v4;
        }
    }
}

// ---------------------------------------------------------------------------
// Final projection: out[i,j] = sum_k concat[i,k] * Wc[j,k] + bc[j]
// concat[i,k] remapped from g_att (b,h,t,e) layout. M=4096, N=512, K=4096.
// ---------------------------------------------------------------------------
__global__ __launch_bounds__(256) void final_kernel(const float* __restrict__ Wc,
                                                    const float* __restrict__ bc,
                                                    float* __restrict__ out)
{
    __shared__ float As[8][128];
    __shared__ float Bs[8][128];

    const int m0 = blockIdx.y * 128;
    const int n0 = blockIdx.x * 128;
    const int tid = threadIdx.x;
    const int tx = tid & 15, ty = tid >> 4;
    const int lrow = tid >> 1;
    const int lk4  = (tid & 1) * 4;

    float acc[8][8];
#pragma unroll
    for (int i = 0; i < 8; i++)
#pragma unroll
        for (int j = 0; j < 8; j++) acc[i][j] = 0.f;

    const int gi = m0 + lrow;             // token index for A loads
    const int bb = gi >> 11, t = gi & 2047;

    for (int k0 = 0; k0 < 4096; k0 += 8) {
        int k = k0 + lk4;
        int h = k >> 9, e = k & 511;
        float4 a = *(const float4*)(g_att + (((bb * 8 + h) * 2048 + t) << 9) + e);
        float4 b = *(const float4*)(Wc + (n0 + lrow) * 4096 + k);
        As[lk4 + 0][lrow] = a.x; As[lk4 + 1][lrow] = a.y;
        As[lk4 + 2][lrow] = a.z; As[lk4 + 3][lrow] = a.w;
        Bs[lk4 + 0][lrow] = b.x; Bs[lk4 + 1][lrow] = b.y;
        Bs[lk4 + 2][lrow] = b.z; Bs[lk4 + 3][lrow] = b.w;
        __syncthreads();
#pragma unroll
        for (int kk = 0; kk < 8; kk++) {
            float a0[8], b0[8];
            *(float4*)&a0[0] = *(const float4*)&As[kk][ty * 8];
            *(float4*)&a0[4] = *(const float4*)&As[kk][ty * 8 + 4];
            *(float4*)&b0[0] = *(const float4*)&Bs[kk][tx * 8];
            *(float4*)&b0[4] = *(const float4*)&Bs[kk][tx * 8 + 4];
#pragma unroll
            for (int i = 0; i < 8; i++)
#pragma unroll
                for (int j = 0; j < 8; j++) acc[i][j] += a0[i] * b0[j];
        }
        __syncthreads();
    }

#pragma unroll
    for (int i = 0; i < 8; i++) {
        int r = m0 + ty * 8 + i;
#pragma unroll
        for (int j4 = 0; j4 < 2; j4++) {
            int c = n0 + tx * 8 + j4 * 4;
            float4 bias = *(const float4*)(bc + c);
            float4 v4 = make_float4(acc[i][j4 * 4 + 0] + bias.x,
                                    acc[i][j4 * 4 + 1] + bias.y,
                                    acc[i][j4 * 4 + 2] + bias.z,
                                    acc[i][j4 * 4 + 3] + bias.w);
            *(float4*)(out + r * 512 + c) = v4;
        }
    }
}

// ---------------------------------------------------------------------------
extern "C" void kernel_launch(void* const* d_in, const int* in_sizes, int n_in,
                              void* d_out, int out_size)
{
    (void)in_sizes; (void)n_in; (void)out_size;
    const float* x  = (const float*)d_in[0];
    const float* Wk = (const float*)d_in[1];
    const float* Wq = (const float*)d_in[2];
    const float* Wv = (const float*)d_in[3];
    const float* Wc = (const float*)d_in[4];
    const float* bc = (const float*)d_in[5];
    float* out = (float*)d_out;

    dim3 blk(256);

    proj_kernel<<<dim3(32, 32), blk>>>(x, Wq, 0);
    proj_kernel<<<dim3(32, 32), blk>>>(x, Wk, 1);
    proj_kernel<<<dim3(32, 32), blk>>>(x, Wv, 2);

    scores_kernel<<<dim3(16, 16, 16), blk>>>();
    softmax_kernel<<<dim3(32768), blk>>>();
    pv_kernel<<<dim3(4, 16, 16), blk>>>();

    final_kernel<<<dim3(4, 32), blk>>>(Wc, bc, out);
}

// round 2
// speedup vs baseline: 2.8394x; 2.8394x over previous
#include <cuda_runtime.h>

// ---------------------------------------------------------------------------
// MultiHeadAttention b=2,t=2048,e=512,h=8 (per-head dim 512)
// Round 2: all GEMMs on TF32 tensor cores (mma.sync m16n8k8), fp32 accumulate.
// 128x128 block tile, BK=16, 8 warps (2x4), warp tile 64x32.
// Smem stride 20 words -> conflict-free fragment LDS (bank map verified).
// ---------------------------------------------------------------------------

#define NEG_INF (-1e30f)
#define SCALE 0.044194173824159216f   // 1/sqrt(512)
#define SSTR 20                       // smem row stride (words)

static __device__ float g_q[16 * 2048 * 512];
static __device__ float g_k[16 * 2048 * 512];
static __device__ float g_v[16 * 2048 * 512];
static __device__ float g_p[16u * 2048 * 2048];
static __device__ float g_att[16 * 2048 * 512];

__device__ __forceinline__ unsigned f2tf(float x) {
    unsigned r; asm("cvt.rna.tf32.f32 %0, %1;" : "=r"(r) : "f"(x)); return r;
}
__device__ __forceinline__ uint4 f4tf(float4 v) {
    return make_uint4(f2tf(v.x), f2tf(v.y), f2tf(v.z), f2tf(v.w));
}
__device__ __forceinline__ void mma8(float* d, const unsigned* a, const unsigned* b) {
    asm volatile("mma.sync.aligned.m16n8k8.row.col.f32.tf32.tf32.f32 "
                 "{%0,%1,%2,%3}, {%4,%5,%6,%7}, {%8,%9}, {%0,%1,%2,%3};"
                 : "+f"(d[0]), "+f"(d[1]), "+f"(d[2]), "+f"(d[3])
                 : "r"(a[0]), "r"(a[1]), "r"(a[2]), "r"(a[3]),
                   "r"(b[0]), "r"(b[1]));
}

// Compute one 128x128x16 tile from smem (As rows 0..127 = M, Bs rows = N,
// both stored [row][k] with stride SSTR).
__device__ __forceinline__ void compute_tile(const unsigned* __restrict__ As,
                                             const unsigned* __restrict__ Bs,
                                             float acc[4][4][4],
                                             int wm, int wn, int g, int tg)
{
#pragma unroll
    for (int kk = 0; kk < 16; kk += 8) {
        unsigned af[4][4];
#pragma unroll
        for (int mi = 0; mi < 4; mi++) {
            const unsigned* p = As + (wm * 64 + mi * 16 + g) * SSTR + kk + tg;
            af[mi][0] = p[0];
            af[mi][1] = p[8 * SSTR];
            af[mi][2] = p[4];
            af[mi][3] = p[8 * SSTR + 4];
        }
        unsigned bf[4][2];
#pragma unroll
        for (int ni = 0; ni < 4; ni++) {
            const unsigned* p = Bs + (wn * 32 + ni * 8 + g) * SSTR + kk + tg;
            bf[ni][0] = p[0];
            bf[ni][1] = p[4];
        }
#pragma unroll
        for (int mi = 0; mi < 4; mi++)
#pragma unroll
            for (int ni = 0; ni < 4; ni++)
                mma8(acc[mi][ni], af[mi], bf[ni]);
    }
}

// ---------------------------------------------------------------------------
// proj: C = X * W^T, M=N=4096, K=512; out remapped to (b,h,t,e)
// ---------------------------------------------------------------------------
__global__ __launch_bounds__(256) void proj_kernel(const float* __restrict__ X,
                                                   const float* __restrict__ W,
                                                   int mode)
{
    __shared__ __align__(16) unsigned As[128 * SSTR];
    __shared__ __align__(16) unsigned Bs[128 * SSTR];
    float* out = (mode == 0) ? g_q : (mode == 1) ? g_k : g_v;

    const int m0 = blockIdx.y * 128, n0 = blockIdx.x * 128;
    const int tid = threadIdx.x;
    const int w = tid >> 5, lane = tid & 31, g = lane >> 2, tg = lane & 3;
    const int wm = w >> 2, wn = w & 3;

    float acc[4][4][4];
#pragma unroll
    for (int i = 0; i < 4; i++)
#pragma unroll
        for (int j = 0; j < 4; j++)
#pragma unroll
            for (int k = 0; k < 4; k++) acc[i][j][k] = 0.f;

    float4 pa[2], pb[2];
#pragma unroll
    for (int it = 0; it < 2; it++) {
        int l = tid + it * 256, row = l >> 2, k4 = (l & 3) * 4;
        pa[it] = *(const float4*)(X + (m0 + row) * 512 + k4);
        pb[it] = *(const float4*)(W + (n0 + row) * 512 + k4);
    }
    for (int kt = 0; kt < 32; kt++) {
#pragma unroll
        for (int it = 0; it < 2; it++) {
            int l = tid + it * 256, row = l >> 2, k4 = (l & 3) * 4;
            *(uint4*)&As[row * SSTR + k4] = f4tf(pa[it]);
            *(uint4*)&Bs[row * SSTR + k4] = f4tf(pb[it]);
        }
        __syncthreads();
        if (kt < 31) {
            int k0 = (kt + 1) * 16;
#pragma unroll
            for (int it = 0; it < 2; it++) {
                int l = tid + it * 256, row = l >> 2, k4 = (l & 3) * 4;
                pa[it] = *(const float4*)(X + (m0 + row) * 512 + k0 + k4);
                pb[it] = *(const float4*)(W + (n0 + row) * 512 + k0 + k4);
            }
        }
        compute_tile(As, Bs, acc, wm, wn, g, tg);
        __syncthreads();
    }

#pragma unroll
    for (int mi = 0; mi < 4; mi++)
#pragma unroll
        for (int ni = 0; ni < 4; ni++) {
            int cbase = n0 + wn * 32 + ni * 8 + 2 * tg;
            int h = cbase >> 9, e = cbase & 511;
#pragma unroll
            for (int rr = 0; rr < 2; rr++) {
                int row = m0 + wm * 64 + mi * 16 + g + rr * 8;
                int bb = row >> 11, t = row & 2047;
                float2 v = make_float2(acc[mi][ni][rr * 2], acc[mi][ni][rr * 2 + 1]);
                *(float2*)(out + (((size_t)(bb * 8 + h) * 2048 + t) << 9) + e) = v;
            }
        }
}

// ---------------------------------------------------------------------------
// scores: per z, S = Q K^T * scale + causal mask. M=N=2048, K=512.
// ---------------------------------------------------------------------------
__global__ __launch_bounds__(256) void scores_kernel()
{
    const int z = blockIdx.z;
    const int m0 = blockIdx.y * 128, n0 = blockIdx.x * 128;
    if (n0 > m0 + 127) return;

    const float* Q = g_q + z * 1048576;
    const float* K = g_k + z * 1048576;
    float* P = g_p + (size_t)z * 4194304;

    __shared__ __align__(16) unsigned As[128 * SSTR];
    __shared__ __align__(16) unsigned Bs[128 * SSTR];

    const int tid = threadIdx.x;
    const int w = tid >> 5, lane = tid & 31, g = lane >> 2, tg = lane & 3;
    const int wm = w >> 2, wn = w & 3;

    float acc[4][4][4];
#pragma unroll
    for (int i = 0; i < 4; i++)
#pragma unroll
        for (int j = 0; j < 4; j++)
#pragma unroll
            for (int k = 0; k < 4; k++) acc[i][j][k] = 0.f;

    float4 pa[2], pb[2];
#pragma unroll
    for (int it = 0; it < 2; it++) {
        int l = tid + it * 256, row = l >> 2, k4 = (l & 3) * 4;
        pa[it] = *(const float4*)(Q + (m0 + row) * 512 + k4);
        pb[it] = *(const float4*)(K + (n0 + row) * 512 + k4);
    }
    for (int kt = 0; kt < 32; kt++) {
#pragma unroll
        for (int it = 0; it < 2; it++) {
            int l = tid + it * 256, row = l >> 2, k4 = (l & 3) * 4;
            *(uint4*)&As[row * SSTR + k4] = f4tf(pa[it]);
            *(uint4*)&Bs[row * SSTR + k4] = f4tf(pb[it]);
        }
        __syncthreads();
        if (kt < 31) {
            int k0 = (kt + 1) * 16;
#pragma unroll
            for (int it = 0; it < 2; it++) {
                int l = tid + it * 256, row = l >> 2, k4 = (l & 3) * 4;
                pa[it] = *(const float4*)(Q + (m0 + row) * 512 + k0 + k4);
                pb[it] = *(const float4*)(K + (n0 + row) * 512 + k0 + k4);
            }
        }
        compute_tile(As, Bs, acc, wm, wn, g, tg);
        __syncthreads();
    }

#pragma unroll
    for (int mi = 0; mi < 4; mi++)
#pragma unroll
        for (int ni = 0; ni < 4; ni++) {
            int col = n0 + wn * 32 + ni * 8 + 2 * tg;
#pragma unroll
            for (int rr = 0; rr < 2; rr++) {
                int row = m0 + wm * 64 + mi * 16 + g + rr * 8;
                float2 v;
                v.x = (col <= row) ? acc[mi][ni][rr * 2] * SCALE : NEG_INF;
                v.y = (col + 1 <= row) ? acc[mi][ni][rr * 2 + 1] * SCALE : NEG_INF;
                *(float2*)(P + (size_t)row * 2048 + col) = v;
            }
        }
}

// ---------------------------------------------------------------------------
// softmax (unchanged from round 1)
// ---------------------------------------------------------------------------
__global__ __launch_bounds__(256) void softmax_kernel()
{
    const int row = blockIdx.x;
    const int z = row >> 11;
    const int q = row & 2047;
    float* P = g_p + (size_t)z * 4194304 + q * 2048;
    const int end = ((q >> 7) + 1) << 7;

    const int tid = threadIdx.x;
    __shared__ float red[256];

    float m = -3.4e38f;
    for (int c = tid; c < end; c += 256) m = fmaxf(m, P[c]);
    red[tid] = m; __syncthreads();
    for (int s = 128; s > 0; s >>= 1) {
        if (tid < s) red[tid] = fmaxf(red[tid], red[tid + s]);
        __syncthreads();
    }
    m = red[0]; __syncthreads();

    float vals[8];
    int cnt = 0;
    float sum = 0.f;
    for (int c = tid; c < end; c += 256) {
        float e = expf(P[c] - m);
        vals[cnt++] = e;
        sum += e;
    }
    red[tid] = sum; __syncthreads();
    for (int s = 128; s > 0; s >>= 1) {
        if (tid < s) red[tid] += red[tid + s];
        __syncthreads();
    }
    const float inv = 1.f / red[0];
    cnt = 0;
    for (int c = tid; c < end; c += 256) P[c] = vals[cnt++] * inv;
}

// ---------------------------------------------------------------------------
// pv: O = P @ V, M=2048, N=512, K truncated at (by+1)*128. V is [k][n]
// row-major, transposed into Bs during smem fill (conflict-free by mapping).
// ---------------------------------------------------------------------------
__global__ __launch_bounds__(256) void pv_kernel()
{
    const int z = blockIdx.z;
    const int m0 = blockIdx.y * 128, n0 = blockIdx.x * 128;
    const int ntiles = (blockIdx.y + 1) * 8;   // kend/16

    const float* P = g_p + (size_t)z * 4194304;
    const float* V = g_v + z * 1048576;
    float* O = g_att + z * 1048576;

    __shared__ __align__(16) unsigned As[128 * SSTR];
    __shared__ __align__(16) unsigned Bs[128 * SSTR];

    const int tid = threadIdx.x;
    const int w = tid >> 5, lane = tid & 31, g = lane >> 2, tg = lane & 3;
    const int wm = w >> 2, wn = w & 3;

    float acc[4][4][4];
#pragma unroll
    for (int i = 0; i < 4; i++)
#pragma unroll
        for (int j = 0; j < 4; j++)
#pragma unroll
            for (int k = 0; k < 4; k++) acc[i][j][k] = 0.f;

    float4 pa[2], pb[2];
#pragma unroll
    for (int it = 0; it < 2; it++) {
        int l = tid + it * 256;
        int arow = l >> 2, ak4 = (l & 3) * 4;
        pa[it] = *(const float4*)(P + (size_t)(m0 + arow) * 2048 + ak4);
        int n4 = l >> 4, kr = l & 15;
        pb[it] = *(const float4*)(V + (size_t)kr * 512 + n0 + n4 * 4);
    }
    for (int kt = 0; kt < ntiles; kt++) {
#pragma unroll
        for (int it = 0; it < 2; it++) {
            int l = tid + it * 256;
            int arow = l >> 2, ak4 = (l & 3) * 4;
            *(uint4*)&As[arow * SSTR + ak4] = f4tf(pa[it]);
            int n4 = l >> 4, kr = l & 15;
            Bs[(n4 * 4 + 0) * SSTR + kr] = f2tf(pb[it].x);
            Bs[(n4 * 4 + 1) * SSTR + kr] = f2tf(pb[it].y);
            Bs[(n4 * 4 + 2) * SSTR + kr] = f2tf(pb[it].z);
            Bs[(n4 * 4 + 3) * SSTR + kr] = f2tf(pb[it].w);
        }
        __syncthreads();
        if (kt < ntiles - 1) {
            int k0 = (kt + 1) * 16;
#pragma unroll
            for (int it = 0; it < 2; it++) {
                int l = tid + it * 256;
                int arow = l >> 2, ak4 = (l & 3) * 4;
                pa[it] = *(const float4*)(P + (size_t)(m0 + arow) * 2048 + k0 + ak4);
                int n4 = l >> 4, kr = l & 15;
                pb[it] = *(const float4*)(V + (size_t)(k0 + kr) * 512 + n0 + n4 * 4);
            }
        }
        compute_tile(As, Bs, acc, wm, wn, g, tg);
        __syncthreads();
    }

#pragma unroll
    for (int mi = 0; mi < 4; mi++)
#pragma unroll
        for (int ni = 0; ni < 4; ni++) {
            int col = n0 + wn * 32 + ni * 8 + 2 * tg;
#pragma unroll
            for (int rr = 0; rr < 2; rr++) {
                int row = m0 + wm * 64 + mi * 16 + g + rr * 8;
                float2 v = make_float2(acc[mi][ni][rr * 2], acc[mi][ni][rr * 2 + 1]);
                *(float2*)(O + row * 512 + col) = v;
            }
        }
}

// ---------------------------------------------------------------------------
// final: out = concat(att) @ Wc^T + bc, M=4096, N=512, K=4096
// ---------------------------------------------------------------------------
__global__ __launch_bounds__(256) void final_kernel(const float* __restrict__ Wc,
                                                    const float* __restrict__ bc,
                                                    float* __restrict__ out)
{
    __shared__ __align__(16) unsigned As[128 * SSTR];
    __shared__ __align__(16) unsigned Bs[128 * SSTR];

    const int m0 = blockIdx.y * 128, n0 = blockIdx.x * 128;
    const int tid = threadIdx.x;
    const int w = tid >> 5, lane = tid & 31, g = lane >> 2, tg = lane & 3;
    const int wm = w >> 2, wn = w & 3;

    float acc[4][4][4];
#pragma unroll
    for (int i = 0; i < 4; i++)
#pragma unroll
        for (int j = 0; j < 4; j++)
#pragma unroll
            for (int k = 0; k < 4; k++) acc[i][j][k] = 0.f;

    float4 pa[2], pb[2];
#pragma unroll
    for (int it = 0; it < 2; it++) {
        int l = tid + it * 256, row = l >> 2, k4 = (l & 3) * 4;
        int gi = m0 + row, bb = gi >> 11, t = gi & 2047;
        int k = k4, h = k >> 9, e = k & 511;
        pa[it] = *(const float4*)(g_att + (((size_t)(bb * 8 + h) * 2048 + t) << 9) + e);
        pb[it] = *(const float4*)(Wc + (size_t)(n0 + row) * 4096 + k4);
    }
    for (int kt = 0; kt < 256; kt++) {
#pragma unroll
        for (int it = 0; it < 2; it++) {
            int l = tid + it * 256, row = l >> 2, k4 = (l & 3) * 4;
            *(uint4*)&As[row * SSTR + k4] = f4tf(pa[it]);
            *(uint4*)&Bs[row * SSTR + k4] = f4tf(pb[it]);
        }
        __syncthreads();
        if (kt < 255) {
            int k0 = (kt + 1) * 16;
#pragma unroll
            for (int it = 0; it < 2; it++) {
                int l = tid + it * 256, row = l >> 2, k4 = (l & 3) * 4;
                int gi = m0 + row, bb = gi >> 11, t = gi & 2047;
                int k = k0 + k4, h = k >> 9, e = k & 511;
                pa[it] = *(const float4*)(g_att + (((size_t)(bb * 8 + h) * 2048 + t) << 9) + e);
                pb[it] = *(const float4*)(Wc + (size_t)(n0 + row) * 4096 + k);
            }
        }
        compute_tile(As, Bs, acc, wm, wn, g, tg);
        __syncthreads();
    }

#pragma unroll
    for (int mi = 0; mi < 4; mi++)
#pragma unroll
        for (int ni = 0; ni < 4; ni++) {
            int col = n0 + wn * 32 + ni * 8 + 2 * tg;
            float2 bias = *(const float2*)(bc + col);
#pragma unroll
            for (int rr = 0; rr < 2; rr++) {
                int row = m0 + wm * 64 + mi * 16 + g + rr * 8;
                float2 v = make_float2(acc[mi][ni][rr * 2] + bias.x,
                                       acc[mi][ni][rr * 2 + 1] + bias.y);
                *(float2*)(out + (size_t)row * 512 + col) = v;
            }
        }
}

// ---------------------------------------------------------------------------
extern "C" void kernel_launch(void* const* d_in, const int* in_sizes, int n_in,
                              void* d_out, int out_size)
{
    (void)in_sizes; (void)n_in; (void)out_size;
    const float* x  = (const float*)d_in[0];
    const float* Wk = (const float*)d_in[1];
    const float* Wq = (const float*)d_in[2];
    const float* Wv = (const float*)d_in[3];
    const float* Wc = (const float*)d_in[4];
    const float* bc = (const float*)d_in[5];
    float* out = (float*)d_out;

    dim3 blk(256);

    proj_kernel<<<dim3(32, 32), blk>>>(x, Wq, 0);
    proj_kernel<<<dim3(32, 32), blk>>>(x, Wk, 1);
    proj_kernel<<<dim3(32, 32), blk>>>(x, Wv, 2);

    scores_kernel<<<dim3(16, 16, 16), blk>>>();
    softmax_kernel<<<dim3(32768), blk>>>();
    pv_kernel<<<dim3(4, 16, 16), blk>>>();

    final_kernel<<<dim3(4, 32), blk>>>(Wc, bc, out);
}